// round 1
// baseline (speedup 1.0000x reference)
#include <cuda_runtime.h>
#include <math.h>
#include <stdint.h>

// Problem constants
#define Bc   2
#define Tc   1024
#define Dc   1024
#define Hc   16
#define HDc  64
#define FFc  4096
#define Lc   2
#define Vc   32000
#define BT   (Bc*Tc)          // 2048 rows

#define EPS_RMS 1.1920929e-07f
#define EPS_LN  1e-5f

// ------------------------- device scratch (static, no allocs) -------------
__device__ float g_x [BT*Dc];
__device__ float g_h [BT*Dc];
__device__ float g_q [BT*Dc];
__device__ float g_k [BT*Dc];
__device__ float g_v [BT*Dc];
__device__ float g_o [BT*Dc];
__device__ float g_a [BT*FFc];
__device__ float g_g [BT*FFc];
__device__ float g_wq[Lc*Dc*Dc];
__device__ float g_wk[Lc*Dc*Dc];
__device__ float g_wv[Lc*Dc*Dc];

// ------------------------- helpers ---------------------------------------
__device__ __forceinline__ float warpMax(float v) {
    #pragma unroll
    for (int o = 16; o; o >>= 1) v = fmaxf(v, __shfl_xor_sync(0xffffffffu, v, o));
    return v;
}
__device__ __forceinline__ float warpSum(float v) {
    #pragma unroll
    for (int o = 16; o; o >>= 1) v += __shfl_xor_sync(0xffffffffu, v, o);
    return v;
}

// ------------------------- repack qkv weights -----------------------------
// src: [L][H][D][HD]  ->  dst: [L][D][H*HD]   (row-major [K,N] per layer)
__global__ void repack_kernel(const float* __restrict__ src, float* __restrict__ dst) {
    int i = blockIdx.x * blockDim.x + threadIdx.x;
    if (i >= Lc * Dc * Dc) return;
    int l   = i / (Dc * Dc);
    int rem = i - l * (Dc * Dc);
    int d   = rem >> 10;
    int c   = rem & 1023;
    int h   = c >> 6;
    int kk  = c & 63;
    dst[i] = src[(size_t)l * Dc * Dc + (size_t)h * Dc * HDc + (size_t)d * HDc + kk];
}

// ------------------------- embedding gather -------------------------------
__global__ void embed_kernel(const int* __restrict__ idx, const float* __restrict__ emb) {
    int i = blockIdx.x * blockDim.x + threadIdx.x;     // BT*Dc
    if (i >= BT * Dc) return;
    int row = i >> 10;
    int d   = i & 1023;
    g_x[i] = emb[(size_t)idx[row] * Dc + d];
}

// ------------------------- RMSNorm (D=1024, 256 threads/row) --------------
__global__ void rmsnorm_kernel(const float* __restrict__ x, const float* __restrict__ w,
                               float* __restrict__ out) {
    int row = blockIdx.x;
    int tid = threadIdx.x;
    const float* xr = x + (size_t)row * Dc;
    float v0 = xr[tid], v1 = xr[tid + 256], v2 = xr[tid + 512], v3 = xr[tid + 768];
    float ss = v0*v0 + v1*v1 + v2*v2 + v3*v3;
    __shared__ float sred[8];
    ss = warpSum(ss);
    if ((tid & 31) == 0) sred[tid >> 5] = ss;
    __syncthreads();
    if (tid == 0) {
        float t = 0.f;
        #pragma unroll
        for (int i = 0; i < 8; i++) t += sred[i];
        sred[0] = rsqrtf(t * (1.0f / Dc) + EPS_RMS);
    }
    __syncthreads();
    float r = sred[0];
    float* orow = out + (size_t)row * Dc;
    orow[tid      ] = v0 * r * w[tid      ];
    orow[tid + 256] = v1 * r * w[tid + 256];
    orow[tid + 512] = v2 * r * w[tid + 512];
    orow[tid + 768] = v3 * r * w[tid + 768];
}

// ------------------------- LayerNorm --------------------------------------
__global__ void layernorm_kernel(const float* __restrict__ x, const float* __restrict__ w,
                                 const float* __restrict__ b, float* __restrict__ out) {
    int row = blockIdx.x;
    int tid = threadIdx.x;
    const float* xr = x + (size_t)row * Dc;
    float v0 = xr[tid], v1 = xr[tid + 256], v2 = xr[tid + 512], v3 = xr[tid + 768];
    __shared__ float sred[8];
    __shared__ float sbc[2];
    float s = v0 + v1 + v2 + v3;
    s = warpSum(s);
    if ((tid & 31) == 0) sred[tid >> 5] = s;
    __syncthreads();
    if (tid == 0) {
        float t = 0.f;
        #pragma unroll
        for (int i = 0; i < 8; i++) t += sred[i];
        sbc[0] = t * (1.0f / Dc);
    }
    __syncthreads();
    float mu = sbc[0];
    float d0 = v0 - mu, d1 = v1 - mu, d2 = v2 - mu, d3 = v3 - mu;
    float sq = d0*d0 + d1*d1 + d2*d2 + d3*d3;
    sq = warpSum(sq);
    if ((tid & 31) == 0) sred[tid >> 5] = sq;
    __syncthreads();
    if (tid == 0) {
        float t = 0.f;
        #pragma unroll
        for (int i = 0; i < 8; i++) t += sred[i];
        sbc[1] = rsqrtf(t * (1.0f / Dc) + EPS_LN);
    }
    __syncthreads();
    float r = sbc[1];
    float* orow = out + (size_t)row * Dc;
    orow[tid      ] = d0 * r * w[tid      ] + b[tid      ];
    orow[tid + 256] = d1 * r * w[tid + 256] + b[tid + 256];
    orow[tid + 512] = d2 * r * w[tid + 512] + b[tid + 512];
    orow[tid + 768] = d3 * r * w[tid + 768] + b[tid + 768];
}

// ------------------------- SiLU(a) * g (in place into a) ------------------
__global__ void silu_mul_kernel(float* __restrict__ a, const float* __restrict__ g, int n) {
    int i = blockIdx.x * blockDim.x + threadIdx.x;
    if (i >= n) return;
    float x = a[i];
    a[i] = (x / (1.0f + expf(-x))) * g[i];
}

// ------------------------- attention (per (b,h,t) row, causal) ------------
// q,k,v,o layout: [B,T,H,HD] flat == row-major [BT, D]
__global__ void attn_kernel(const float* __restrict__ q, const float* __restrict__ k,
                            const float* __restrict__ v, float* __restrict__ o) {
    int t   = blockIdx.x;          // 0..T-1
    int bh  = blockIdx.y;          // b*H + h
    int b   = bh >> 4;
    int h   = bh & 15;
    int tid = threadIdx.x;         // 256 threads

    __shared__ float qs[HDc];
    __shared__ float sc[Tc];
    __shared__ float red1[8];
    __shared__ float red2[8];
    __shared__ float bc[2];
    __shared__ float opart[4][HDc];

    const size_t qrow = ((size_t)(b * Tc + t) * Hc + h) * HDc;
    if (tid < HDc) qs[tid] = q[qrow + tid];
    __syncthreads();

    // pass 1: scores
    float lmax = -INFINITY;
    for (int s = tid; s <= t; s += 256) {
        const float* kr = k + ((size_t)(b * Tc + s) * Hc + h) * HDc;
        float acc = 0.f;
        #pragma unroll
        for (int d = 0; d < HDc; d++) acc = fmaf(qs[d], kr[d], acc);
        acc *= 0.125f;               // 1/sqrt(64)
        sc[s] = acc;
        lmax = fmaxf(lmax, acc);
    }
    // block max
    lmax = warpMax(lmax);
    if ((tid & 31) == 0) red1[tid >> 5] = lmax;
    __syncthreads();
    if (tid == 0) {
        float m = red1[0];
        #pragma unroll
        for (int i = 1; i < 8; i++) m = fmaxf(m, red1[i]);
        bc[0] = m;
    }
    __syncthreads();
    float mx = bc[0];

    // exponentiate + sum
    float lsum = 0.f;
    for (int s = tid; s <= t; s += 256) {
        float p = expf(sc[s] - mx);
        sc[s] = p;
        lsum += p;
    }
    lsum = warpSum(lsum);
    if ((tid & 31) == 0) red2[tid >> 5] = lsum;
    __syncthreads();
    if (tid == 0) {
        float ssum = 0.f;
        #pragma unroll
        for (int i = 0; i < 8; i++) ssum += red2[i];
        bc[1] = 1.0f / ssum;
    }
    __syncthreads();
    float inv = bc[1];

    // pass 2: o[d] = sum_s p[s] * v[s,d]
    int part = tid >> 6;           // 0..3
    int d    = tid & 63;
    float acc = 0.f;
    for (int s = part; s <= t; s += 4) {
        acc = fmaf(sc[s], v[((size_t)(b * Tc + s) * Hc + h) * HDc + d], acc);
    }
    opart[part][d] = acc;
    __syncthreads();
    if (tid < HDc) {
        float val = (opart[0][tid] + opart[1][tid] + opart[2][tid] + opart[3][tid]) * inv;
        o[qrow + tid] = val;
    }
}

// ------------------------- SGEMM: C[M,N] = A[M,K] @ B[K,N] (+bias)(+resid)-
// 128x128 block tile, BK=8, 256 threads, 8x8 per thread.
// Requires M%128==0, N%128==0, K%8==0 (true for all calls here).
__global__ void __launch_bounds__(256) sgemm_kernel(
    const float* __restrict__ A, const float* __restrict__ B,
    const float* __restrict__ bias, float* __restrict__ C,
    int M, int N, int K, int addResid)
{
    __shared__ float As[8][128];
    __shared__ float Bs[8][128];

    int tid = threadIdx.x;
    int m0 = blockIdx.y * 128;
    int n0 = blockIdx.x * 128;
    int ty = tid >> 4;       // 0..15
    int tx = tid & 15;       // 0..15

    int arow = tid >> 1;           // 0..127
    int acol = (tid & 1) * 4;      // 0 or 4
    int brow = tid >> 5;           // 0..7
    int bcol = (tid & 31) * 4;     // 0..124

    const float* Aptr = A + (size_t)(m0 + arow) * K + acol;
    const float* Bptr = B + (size_t)brow * N + (n0 + bcol);

    float acc[8][8];
    #pragma unroll
    for (int i = 0; i < 8; i++)
        #pragma unroll
        for (int j = 0; j < 8; j++) acc[i][j] = 0.f;

    for (int k0 = 0; k0 < K; k0 += 8) {
        float4 av = *(const float4*)(Aptr + k0);
        float4 bv = *(const float4*)(Bptr + (size_t)k0 * N);
        As[acol + 0][arow] = av.x;
        As[acol + 1][arow] = av.y;
        As[acol + 2][arow] = av.z;
        As[acol + 3][arow] = av.w;
        *(float4*)&Bs[brow][bcol] = bv;
        __syncthreads();

        #pragma unroll
        for (int kk = 0; kk < 8; kk++) {
            float4 a0 = *(const float4*)&As[kk][ty * 8];
            float4 a1 = *(const float4*)&As[kk][ty * 8 + 4];
            float4 b0 = *(const float4*)&Bs[kk][tx * 8];
            float4 b1 = *(const float4*)&Bs[kk][tx * 8 + 4];
            float ar[8] = {a0.x, a0.y, a0.z, a0.w, a1.x, a1.y, a1.z, a1.w};
            float br[8] = {b0.x, b0.y, b0.z, b0.w, b1.x, b1.y, b1.z, b1.w};
            #pragma unroll
            for (int i = 0; i < 8; i++)
                #pragma unroll
                for (int j = 0; j < 8; j++)
                    acc[i][j] = fmaf(ar[i], br[j], acc[i][j]);
        }
        __syncthreads();
    }

    // epilogue
    float bvals[8];
    #pragma unroll
    for (int j = 0; j < 8; j++)
        bvals[j] = bias ? bias[n0 + tx * 8 + j] : 0.f;

    #pragma unroll
    for (int i = 0; i < 8; i++) {
        int row = m0 + ty * 8 + i;
        float* crow = C + (size_t)row * N + n0 + tx * 8;
        if (addResid) {
            #pragma unroll
            for (int j = 0; j < 8; j++) crow[j] = crow[j] + acc[i][j] + bvals[j];
        } else {
            #pragma unroll
            for (int j = 0; j < 8; j++) crow[j] = acc[i][j] + bvals[j];
        }
    }
}

// ------------------------- host orchestration -----------------------------
extern "C" void kernel_launch(void* const* d_in, const int* in_sizes, int n_in,
                              void* d_out, int out_size) {
    const int*   idx    = (const int*)  d_in[0];
    const float* emb    = (const float*)d_in[1];
    const float* wq     = (const float*)d_in[2];
    const float* wk     = (const float*)d_in[3];
    const float* wv     = (const float*)d_in[4];
    const float* attn_w = (const float*)d_in[5];
    const float* attn_b = (const float*)d_in[6];
    const float* n1_w   = (const float*)d_in[7];
    const float* n2_w   = (const float*)d_in[8];
    const float* f1_w   = (const float*)d_in[9];
    const float* f1_b   = (const float*)d_in[10];
    const float* fs_w   = (const float*)d_in[11];
    const float* fs_b   = (const float*)d_in[12];
    const float* f2_w   = (const float*)d_in[13];
    const float* f2_b   = (const float*)d_in[14];
    const float* ln_w   = (const float*)d_in[15];
    const float* ln_b   = (const float*)d_in[16];
    const float* out_w  = (const float*)d_in[17];
    const float* out_b  = (const float*)d_in[18];

    float *x, *h, *q, *k, *v, *o, *a, *g, *pwq, *pwk, *pwv;
    cudaGetSymbolAddress((void**)&x,   g_x);
    cudaGetSymbolAddress((void**)&h,   g_h);
    cudaGetSymbolAddress((void**)&q,   g_q);
    cudaGetSymbolAddress((void**)&k,   g_k);
    cudaGetSymbolAddress((void**)&v,   g_v);
    cudaGetSymbolAddress((void**)&o,   g_o);
    cudaGetSymbolAddress((void**)&a,   g_a);
    cudaGetSymbolAddress((void**)&g,   g_g);
    cudaGetSymbolAddress((void**)&pwq, g_wq);
    cudaGetSymbolAddress((void**)&pwk, g_wk);
    cudaGetSymbolAddress((void**)&pwv, g_wv);

    const int nRepack = Lc * Dc * Dc;
    repack_kernel<<<(nRepack + 255) / 256, 256>>>(wq, pwq);
    repack_kernel<<<(nRepack + 255) / 256, 256>>>(wk, pwk);
    repack_kernel<<<(nRepack + 255) / 256, 256>>>(wv, pwv);

    embed_kernel<<<(BT * Dc) / 256, 256>>>(idx, emb);

    dim3 gD(Dc / 128, BT / 128);     // N=1024 GEMMs
    dim3 gF(FFc / 128, BT / 128);    // N=4096 GEMMs
    dim3 gV(Vc / 128, BT / 128);     // logits

    for (int l = 0; l < Lc; l++) {
        rmsnorm_kernel<<<BT, 256>>>(x, n1_w + (size_t)l * Dc, h);

        sgemm_kernel<<<gD, 256>>>(h, pwq + (size_t)l * Dc * Dc, nullptr, q, BT, Dc, Dc, 0);
        sgemm_kernel<<<gD, 256>>>(h, pwk + (size_t)l * Dc * Dc, nullptr, k, BT, Dc, Dc, 0);
        sgemm_kernel<<<gD, 256>>>(h, pwv + (size_t)l * Dc * Dc, nullptr, v, BT, Dc, Dc, 0);
        // NOTE: rope diagonal is all-ones (theta = x // HD == 0), so K is unchanged.

        attn_kernel<<<dim3(Tc, Bc * Hc), 256>>>(q, k, v, o);

        sgemm_kernel<<<gD, 256>>>(o, attn_w + (size_t)l * Dc * Dc,
                                  attn_b + (size_t)l * Dc, x, BT, Dc, Dc, 1);

        rmsnorm_kernel<<<BT, 256>>>(x, n2_w + (size_t)l * Dc, h);

        sgemm_kernel<<<gF, 256>>>(h, f1_w + (size_t)l * Dc * FFc,
                                  f1_b + (size_t)l * FFc, a, BT, FFc, Dc, 0);
        sgemm_kernel<<<gF, 256>>>(a, fs_w + (size_t)l * FFc * FFc,
                                  fs_b + (size_t)l * FFc, g, BT, FFc, FFc, 0);
        silu_mul_kernel<<<(BT * FFc) / 256, 256>>>(a, g, BT * FFc);
        sgemm_kernel<<<gD, 256>>>(a, f2_w + (size_t)l * FFc * Dc,
                                  f2_b + (size_t)l * Dc, x, BT, Dc, FFc, 1);
    }

    layernorm_kernel<<<BT, 256>>>(x, ln_w, ln_b, h);
    sgemm_kernel<<<gV, 256>>>(h, out_w, out_b, (float*)d_out, BT, Vc, Dc, 0);
}

// round 6
// speedup vs baseline: 2.4229x; 2.4229x over previous
#include <cuda_runtime.h>
#include <cuda_bf16.h>
#include <math.h>
#include <stdint.h>

// Problem constants
#define Bc   2
#define Tc   1024
#define Dc   1024
#define Hc   16
#define HDc  64
#define FFc  4096
#define Lc   2
#define Vc   32000
#define BT   (Bc*Tc)          // 2048 rows

#define EPS_RMS 1.1920929e-07f
#define EPS_LN  1e-5f

// ------------------------- device scratch (static, no allocs) -------------
__device__ float g_x [BT*Dc];
__device__ float g_h [BT*Dc];
__device__ float g_q [BT*Dc];
__device__ float g_k [BT*Dc];
__device__ float g_v [BT*Dc];
__device__ float g_o [BT*Dc];
__device__ float g_a [BT*FFc];
__device__ float g_g [BT*FFc];
__device__ float g_wq[Lc*Dc*Dc];
__device__ float g_wk[Lc*Dc*Dc];
__device__ float g_wv[Lc*Dc*Dc];

// bf16 hi/lo split weights: per (K,N) matrix, layout [2][K/2][N] uint32
// (each uint32 packs bf16 pair along k). Per-layer size = K*N uint32.
__device__ uint32_t g_swq [Lc*Dc*Dc];
__device__ uint32_t g_swk [Lc*Dc*Dc];
__device__ uint32_t g_swv [Lc*Dc*Dc];
__device__ uint32_t g_swo [Lc*Dc*Dc];
__device__ uint32_t g_sf1 [Lc*Dc*FFc];
__device__ uint32_t g_sfs [Lc*FFc*FFc];
__device__ uint32_t g_sf2 [Lc*FFc*Dc];
__device__ uint32_t g_sout[Dc*Vc];

// ------------------------- helpers ---------------------------------------
__device__ __forceinline__ float warpMax(float v) {
    #pragma unroll
    for (int o = 16; o; o >>= 1) v = fmaxf(v, __shfl_xor_sync(0xffffffffu, v, o));
    return v;
}
__device__ __forceinline__ float warpSum(float v) {
    #pragma unroll
    for (int o = 16; o; o >>= 1) v += __shfl_xor_sync(0xffffffffu, v, o);
    return v;
}
// split two consecutive-k floats into packed bf16 hi and lo pairs
__device__ __forceinline__ void split2(float x0, float x1, uint32_t& hi, uint32_t& lo) {
    __nv_bfloat162 h = __floats2bfloat162_rn(x0, x1);
    float r0 = x0 - __bfloat162float(h.x);
    float r1 = x1 - __bfloat162float(h.y);
    __nv_bfloat162 l = __floats2bfloat162_rn(r0, r1);
    hi = *(uint32_t*)&h;
    lo = *(uint32_t*)&l;
}
__device__ __forceinline__ void mma_bf16(float* c, const uint32_t* a, const uint32_t* b) {
    asm volatile(
        "mma.sync.aligned.m16n8k16.row.col.f32.bf16.bf16.f32 "
        "{%0,%1,%2,%3}, {%4,%5,%6,%7}, {%8,%9}, {%0,%1,%2,%3};"
        : "+f"(c[0]), "+f"(c[1]), "+f"(c[2]), "+f"(c[3])
        : "r"(a[0]), "r"(a[1]), "r"(a[2]), "r"(a[3]),
          "r"(b[0]), "r"(b[1]));
}

// ------------------------- repack qkv weights -----------------------------
// src: [L][H][D][HD]  ->  dst: [L][D][H*HD]   (row-major [K,N] per layer)
__global__ void repack_kernel(const float* __restrict__ src, float* __restrict__ dst) {
    int i = blockIdx.x * blockDim.x + threadIdx.x;
    if (i >= Lc * Dc * Dc) return;
    int l   = i / (Dc * Dc);
    int rem = i - l * (Dc * Dc);
    int d   = rem >> 10;
    int c   = rem & 1023;
    int h   = c >> 6;
    int kk  = c & 63;
    dst[i] = src[(size_t)l * Dc * Dc + (size_t)h * Dc * HDc + (size_t)d * HDc + kk];
}

// ------------------------- weight hi/lo split -----------------------------
// W: fp32 [K][N] row-major -> S: uint32 [2][K/2][N]
__global__ void wsplit_kernel(const float* __restrict__ W, uint32_t* __restrict__ S,
                              int K, int N) {
    int i = blockIdx.x * blockDim.x + threadIdx.x;
    int total = (K >> 1) * N;
    if (i >= total) return;
    int kp = i / N;
    int n  = i - kp * N;
    float x0 = W[(size_t)(2 * kp)     * N + n];
    float x1 = W[(size_t)(2 * kp + 1) * N + n];
    uint32_t hi, lo;
    split2(x0, x1, hi, lo);
    S[i]         = hi;
    S[total + i] = lo;
}

// ------------------------- embedding gather -------------------------------
__global__ void embed_kernel(const int* __restrict__ idx, const float* __restrict__ emb) {
    int i = blockIdx.x * blockDim.x + threadIdx.x;     // BT*Dc
    if (i >= BT * Dc) return;
    int row = i >> 10;
    int d   = i & 1023;
    g_x[i] = emb[(size_t)idx[row] * Dc + d];
}

// ------------------------- RMSNorm (D=1024, 256 threads/row) --------------
__global__ void rmsnorm_kernel(const float* __restrict__ x, const float* __restrict__ w,
                               float* __restrict__ out) {
    int row = blockIdx.x;
    int tid = threadIdx.x;
    const float* xr = x + (size_t)row * Dc;
    float v0 = xr[tid], v1 = xr[tid + 256], v2 = xr[tid + 512], v3 = xr[tid + 768];
    float ss = v0*v0 + v1*v1 + v2*v2 + v3*v3;
    __shared__ float sred[8];
    ss = warpSum(ss);
    if ((tid & 31) == 0) sred[tid >> 5] = ss;
    __syncthreads();
    if (tid == 0) {
        float t = 0.f;
        #pragma unroll
        for (int i = 0; i < 8; i++) t += sred[i];
        sred[0] = rsqrtf(t * (1.0f / Dc) + EPS_RMS);
    }
    __syncthreads();
    float r = sred[0];
    float* orow = out + (size_t)row * Dc;
    orow[tid      ] = v0 * r * w[tid      ];
    orow[tid + 256] = v1 * r * w[tid + 256];
    orow[tid + 512] = v2 * r * w[tid + 512];
    orow[tid + 768] = v3 * r * w[tid + 768];
}

// ------------------------- LayerNorm --------------------------------------
__global__ void layernorm_kernel(const float* __restrict__ x, const float* __restrict__ w,
                                 const float* __restrict__ b, float* __restrict__ out) {
    int row = blockIdx.x;
    int tid = threadIdx.x;
    const float* xr = x + (size_t)row * Dc;
    float v0 = xr[tid], v1 = xr[tid + 256], v2 = xr[tid + 512], v3 = xr[tid + 768];
    __shared__ float sred[8];
    __shared__ float sbc[2];
    float s = v0 + v1 + v2 + v3;
    s = warpSum(s);
    if ((tid & 31) == 0) sred[tid >> 5] = s;
    __syncthreads();
    if (tid == 0) {
        float t = 0.f;
        #pragma unroll
        for (int i = 0; i < 8; i++) t += sred[i];
        sbc[0] = t * (1.0f / Dc);
    }
    __syncthreads();
    float mu = sbc[0];
    float d0 = v0 - mu, d1 = v1 - mu, d2 = v2 - mu, d3 = v3 - mu;
    float sq = d0*d0 + d1*d1 + d2*d2 + d3*d3;
    sq = warpSum(sq);
    if ((tid & 31) == 0) sred[tid >> 5] = sq;
    __syncthreads();
    if (tid == 0) {
        float t = 0.f;
        #pragma unroll
        for (int i = 0; i < 8; i++) t += sred[i];
        sbc[1] = rsqrtf(t * (1.0f / Dc) + EPS_LN);
    }
    __syncthreads();
    float r = sbc[1];
    float* orow = out + (size_t)row * Dc;
    orow[tid      ] = d0 * r * w[tid      ] + b[tid      ];
    orow[tid + 256] = d1 * r * w[tid + 256] + b[tid + 256];
    orow[tid + 512] = d2 * r * w[tid + 512] + b[tid + 512];
    orow[tid + 768] = d3 * r * w[tid + 768] + b[tid + 768];
}

// ------------------------- SiLU(a) * g (in place into a) ------------------
__global__ void silu_mul_kernel(float* __restrict__ a, const float* __restrict__ g, int n) {
    int i = blockIdx.x * blockDim.x + threadIdx.x;
    if (i >= n) return;
    float x = a[i];
    a[i] = (x / (1.0f + expf(-x))) * g[i];
}

// ------------------------- attention (per (b,h,t) row, causal) ------------
// q,k,v,o layout: [B,T,H,HD] flat == row-major [BT, D]
__global__ void attn_kernel(const float* __restrict__ q, const float* __restrict__ k,
                            const float* __restrict__ v, float* __restrict__ o) {
    int t   = blockIdx.x;          // 0..T-1
    int bh  = blockIdx.y;          // b*H + h
    int b   = bh >> 4;
    int h   = bh & 15;
    int tid = threadIdx.x;         // 256 threads

    __shared__ float qs[HDc];
    __shared__ float sc[Tc];
    __shared__ float red1[8];
    __shared__ float red2[8];
    __shared__ float bc[2];
    __shared__ float opart[4][HDc];

    const size_t qrow = ((size_t)(b * Tc + t) * Hc + h) * HDc;
    if (tid < HDc) qs[tid] = q[qrow + tid];
    __syncthreads();

    // pass 1: scores (vectorized dot)
    float lmax = -INFINITY;
    const float4* qs4 = (const float4*)qs;
    for (int s = tid; s <= t; s += 256) {
        const float4* kr4 = (const float4*)(k + ((size_t)(b * Tc + s) * Hc + h) * HDc);
        float acc = 0.f;
        #pragma unroll
        for (int d = 0; d < HDc / 4; d++) {
            float4 kv = kr4[d];
            float4 qv = qs4[d];
            acc = fmaf(qv.x, kv.x, acc);
            acc = fmaf(qv.y, kv.y, acc);
            acc = fmaf(qv.z, kv.z, acc);
            acc = fmaf(qv.w, kv.w, acc);
        }
        acc *= 0.125f;               // 1/sqrt(64)
        sc[s] = acc;
        lmax = fmaxf(lmax, acc);
    }
    lmax = warpMax(lmax);
    if ((tid & 31) == 0) red1[tid >> 5] = lmax;
    __syncthreads();
    if (tid == 0) {
        float m = red1[0];
        #pragma unroll
        for (int i = 1; i < 8; i++) m = fmaxf(m, red1[i]);
        bc[0] = m;
    }
    __syncthreads();
    float mx = bc[0];

    float lsum = 0.f;
    for (int s = tid; s <= t; s += 256) {
        float p = expf(sc[s] - mx);
        sc[s] = p;
        lsum += p;
    }
    lsum = warpSum(lsum);
    if ((tid & 31) == 0) red2[tid >> 5] = lsum;
    __syncthreads();
    if (tid == 0) {
        float ssum = 0.f;
        #pragma unroll
        for (int i = 0; i < 8; i++) ssum += red2[i];
        bc[1] = 1.0f / ssum;
    }
    __syncthreads();
    float inv = bc[1];

    // pass 2: o[d] = sum_s p[s] * v[s,d]
    int part = tid >> 6;           // 0..3
    int d    = tid & 63;
    float acc = 0.f;
    for (int s = part; s <= t; s += 4) {
        acc = fmaf(sc[s], v[((size_t)(b * Tc + s) * Hc + h) * HDc + d], acc);
    }
    opart[part][d] = acc;
    __syncthreads();
    if (tid < HDc) {
        float val = (opart[0][tid] + opart[1][tid] + opart[2][tid] + opart[3][tid]) * inv;
        o[qrow + tid] = val;
    }
}

// ------------------------- bf16x3 tensor-core GEMM ------------------------
// C[M,N] = A[M,K] @ B[K,N] (+bias) (+residual)
// A: fp32 (split to bf16 hi/lo on the fly)
// Bsp: pre-split uint32 [2][K/2][N] bf16 k-pair planes
// 128x128 CTA tile, BK=16, 256 threads (8 warps, 4x2, 32x64 per warp).
// Computes Ah*Bh + Ah*Bl + Al*Bh with fp32 accumulate.
#define SP 9
__global__ void __launch_bounds__(256) bgemm_kernel(
    const float* __restrict__ A, const uint32_t* __restrict__ Bsp,
    const float* __restrict__ bias, float* __restrict__ C,
    int M, int N, int K, int addResid)
{
    // [buf][Ah=0, Al=1, Bh=2, Bl=3][128*SP]
    __shared__ uint32_t sm[2][4][128 * SP];

    int tid  = threadIdx.x;
    int wid  = tid >> 5;
    int lane = tid & 31;
    int gID  = lane >> 2;          // 0..7
    int tg   = lane & 3;           // 0..3

    int wm = (wid & 3) * 32;
    int wn = (wid >> 2) * 64;

    int m0 = blockIdx.y * 128;
    int n0 = blockIdx.x * 128;

    float acc[2][8][4];
    #pragma unroll
    for (int i = 0; i < 2; i++)
        #pragma unroll
        for (int j = 0; j < 8; j++)
            #pragma unroll
            for (int r = 0; r < 4; r++) acc[i][j][r] = 0.f;

    // load mapping
    int la_m  = tid >> 1;           // 0..127
    int la_kp = (tid & 1) * 4;      // kpair 0 or 4
    int lb_n  = tid & 127;          // 0..127
    int lb_kp = (tid >> 7) * 4;     // kpair 0 or 4

    const float* Ag = A + (size_t)(m0 + la_m) * K + la_kp * 2;
    size_t plane = (size_t)(K >> 1) * N;
    const uint32_t* Bh_g = Bsp + (size_t)lb_kp * N + n0 + lb_n;
    const uint32_t* Bl_g = Bh_g + plane;

    int nCh = K >> 4;

    // prologue: chunk 0 -> buffer 0
    {
        float4 a0 = *(const float4*)(Ag);
        float4 a1 = *(const float4*)(Ag + 4);
        float vv[8] = {a0.x, a0.y, a0.z, a0.w, a1.x, a1.y, a1.z, a1.w};
        #pragma unroll
        for (int jp = 0; jp < 4; jp++) {
            uint32_t hi, lo;
            split2(vv[2 * jp], vv[2 * jp + 1], hi, lo);
            sm[0][0][la_m * SP + la_kp + jp] = hi;
            sm[0][1][la_m * SP + la_kp + jp] = lo;
        }
        #pragma unroll
        for (int jp = 0; jp < 4; jp++) {
            sm[0][2][lb_n * SP + lb_kp + jp] = Bh_g[(size_t)jp * N];
            sm[0][3][lb_n * SP + lb_kp + jp] = Bl_g[(size_t)jp * N];
        }
    }
    __syncthreads();

    for (int ch = 0; ch < nCh; ch++) {
        int buf = ch & 1;

        // prefetch next chunk into registers
        float4 pa0, pa1;
        uint32_t pbh[4], pbl[4];
        if (ch + 1 < nCh) {
            const float* Agn = Ag + (ch + 1) * 16;
            pa0 = *(const float4*)(Agn);
            pa1 = *(const float4*)(Agn + 4);
            size_t bo = (size_t)(ch + 1) * 8 * N;
            #pragma unroll
            for (int jp = 0; jp < 4; jp++) {
                pbh[jp] = Bh_g[bo + (size_t)jp * N];
                pbl[jp] = Bl_g[bo + (size_t)jp * N];
            }
        }

        // compute on current buffer (one k16 MMA step)
        uint32_t ah[2][4], al[2][4];
        #pragma unroll
        for (int i = 0; i < 2; i++) {
            int mr = wm + 16 * i + gID;
            ah[i][0] = sm[buf][0][ mr      * SP + tg    ];
            ah[i][1] = sm[buf][0][(mr + 8) * SP + tg    ];
            ah[i][2] = sm[buf][0][ mr      * SP + tg + 4];
            ah[i][3] = sm[buf][0][(mr + 8) * SP + tg + 4];
            al[i][0] = sm[buf][1][ mr      * SP + tg    ];
            al[i][1] = sm[buf][1][(mr + 8) * SP + tg    ];
            al[i][2] = sm[buf][1][ mr      * SP + tg + 4];
            al[i][3] = sm[buf][1][(mr + 8) * SP + tg + 4];
        }
        #pragma unroll
        for (int j = 0; j < 8; j++) {
            int nc = wn + 8 * j + gID;
            uint32_t bh[2], bl[2];
            bh[0] = sm[buf][2][nc * SP + tg    ];
            bh[1] = sm[buf][2][nc * SP + tg + 4];
            bl[0] = sm[buf][3][nc * SP + tg    ];
            bl[1] = sm[buf][3][nc * SP + tg + 4];
            #pragma unroll
            for (int i = 0; i < 2; i++) {
                mma_bf16(acc[i][j], ah[i], bh);
                mma_bf16(acc[i][j], ah[i], bl);
                mma_bf16(acc[i][j], al[i], bh);
            }
        }

        // store prefetched chunk into other buffer
        if (ch + 1 < nCh) {
            int ob = buf ^ 1;
            float vv[8] = {pa0.x, pa0.y, pa0.z, pa0.w, pa1.x, pa1.y, pa1.z, pa1.w};
            #pragma unroll
            for (int jp = 0; jp < 4; jp++) {
                uint32_t hi, lo;
                split2(vv[2 * jp], vv[2 * jp + 1], hi, lo);
                sm[ob][0][la_m * SP + la_kp + jp] = hi;
                sm[ob][1][la_m * SP + la_kp + jp] = lo;
            }
            #pragma unroll
            for (int jp = 0; jp < 4; jp++) {
                sm[ob][2][lb_n * SP + lb_kp + jp] = pbh[jp];
                sm[ob][3][lb_n * SP + lb_kp + jp] = pbl[jp];
            }
        }
        __syncthreads();
    }

    // epilogue
    #pragma unroll
    for (int i = 0; i < 2; i++) {
        int r0 = m0 + wm + 16 * i + gID;
        #pragma unroll
        for (int j = 0; j < 8; j++) {
            int c = n0 + wn + 8 * j + 2 * tg;
            float b0 = bias ? bias[c]     : 0.f;
            float b1 = bias ? bias[c + 1] : 0.f;
            float* p0 = C + (size_t)r0 * N + c;
            float* p1 = C + (size_t)(r0 + 8) * N + c;
            if (addResid) {
                p0[0] += acc[i][j][0] + b0;
                p0[1] += acc[i][j][1] + b1;
                p1[0] += acc[i][j][2] + b0;
                p1[1] += acc[i][j][3] + b1;
            } else {
                p0[0] = acc[i][j][0] + b0;
                p0[1] = acc[i][j][1] + b1;
                p1[0] = acc[i][j][2] + b0;
                p1[1] = acc[i][j][3] + b1;
            }
        }
    }
}

// ------------------------- host orchestration -----------------------------
extern "C" void kernel_launch(void* const* d_in, const int* in_sizes, int n_in,
                              void* d_out, int out_size) {
    const int*   idx    = (const int*)  d_in[0];
    const float* emb    = (const float*)d_in[1];
    const float* wq     = (const float*)d_in[2];
    const float* wk     = (const float*)d_in[3];
    const float* wv     = (const float*)d_in[4];
    const float* attn_w = (const float*)d_in[5];
    const float* attn_b = (const float*)d_in[6];
    const float* n1_w   = (const float*)d_in[7];
    const float* n2_w   = (const float*)d_in[8];
    const float* f1_w   = (const float*)d_in[9];
    const float* f1_b   = (const float*)d_in[10];
    const float* fs_w   = (const float*)d_in[11];
    const float* fs_b   = (const float*)d_in[12];
    const float* f2_w   = (const float*)d_in[13];
    const float* f2_b   = (const float*)d_in[14];
    const float* ln_w   = (const float*)d_in[15];
    const float* ln_b   = (const float*)d_in[16];
    const float* out_w  = (const float*)d_in[17];
    const float* out_b  = (const float*)d_in[18];

    float *x, *h, *q, *k, *v, *o, *a, *g, *pwq, *pwk, *pwv;
    uint32_t *swq, *swk, *swv, *swo, *sf1, *sfs, *sf2, *sout;
    cudaGetSymbolAddress((void**)&x,   g_x);
    cudaGetSymbolAddress((void**)&h,   g_h);
    cudaGetSymbolAddress((void**)&q,   g_q);
    cudaGetSymbolAddress((void**)&k,   g_k);
    cudaGetSymbolAddress((void**)&v,   g_v);
    cudaGetSymbolAddress((void**)&o,   g_o);
    cudaGetSymbolAddress((void**)&a,   g_a);
    cudaGetSymbolAddress((void**)&g,   g_g);
    cudaGetSymbolAddress((void**)&pwq, g_wq);
    cudaGetSymbolAddress((void**)&pwk, g_wk);
    cudaGetSymbolAddress((void**)&pwv, g_wv);
    cudaGetSymbolAddress((void**)&swq, g_swq);
    cudaGetSymbolAddress((void**)&swk, g_swk);
    cudaGetSymbolAddress((void**)&swv, g_swv);
    cudaGetSymbolAddress((void**)&swo, g_swo);
    cudaGetSymbolAddress((void**)&sf1, g_sf1);
    cudaGetSymbolAddress((void**)&sfs, g_sfs);
    cudaGetSymbolAddress((void**)&sf2, g_sf2);
    cudaGetSymbolAddress((void**)&sout, g_sout);

    const int nRepack = Lc * Dc * Dc;
    repack_kernel<<<(nRepack + 255) / 256, 256>>>(wq, pwq);
    repack_kernel<<<(nRepack + 255) / 256, 256>>>(wk, pwk);
    repack_kernel<<<(nRepack + 255) / 256, 256>>>(wv, pwv);

    // weight splits
    for (int l = 0; l < Lc; l++) {
        size_t oDD = (size_t)l * Dc * Dc;
        size_t oDF = (size_t)l * Dc * FFc;
        size_t oFF = (size_t)l * FFc * FFc;
        int nDD = (Dc / 2) * Dc,  nDF = (Dc / 2) * FFc;
        int nFF = (FFc / 2) * FFc, nFD = (FFc / 2) * Dc;
        wsplit_kernel<<<(nDD + 255) / 256, 256>>>(pwq + oDD,    swq + oDD, Dc, Dc);
        wsplit_kernel<<<(nDD + 255) / 256, 256>>>(pwk + oDD,    swk + oDD, Dc, Dc);
        wsplit_kernel<<<(nDD + 255) / 256, 256>>>(pwv + oDD,    swv + oDD, Dc, Dc);
        wsplit_kernel<<<(nDD + 255) / 256, 256>>>(attn_w + oDD, swo + oDD, Dc, Dc);
        wsplit_kernel<<<(nDF + 255) / 256, 256>>>(f1_w + oDF,   sf1 + oDF, Dc, FFc);
        wsplit_kernel<<<(nFF + 255) / 256, 256>>>(fs_w + oFF,   sfs + oFF, FFc, FFc);
        wsplit_kernel<<<(nFD + 255) / 256, 256>>>(f2_w + (size_t)l * FFc * Dc,
                                                  sf2 + (size_t)l * FFc * Dc, FFc, Dc);
    }
    {
        int nOV = (Dc / 2) * Vc;
        wsplit_kernel<<<(nOV + 255) / 256, 256>>>(out_w, sout, Dc, Vc);
    }

    embed_kernel<<<(BT * Dc) / 256, 256>>>(idx, emb);

    dim3 gD(Dc / 128, BT / 128);     // N=1024 GEMMs
    dim3 gF(FFc / 128, BT / 128);    // N=4096 GEMMs
    dim3 gV(Vc / 128, BT / 128);     // logits

    for (int l = 0; l < Lc; l++) {
        size_t oDD = (size_t)l * Dc * Dc;
        rmsnorm_kernel<<<BT, 256>>>(x, n1_w + (size_t)l * Dc, h);

        bgemm_kernel<<<gD, 256>>>(h, swq + oDD, nullptr, q, BT, Dc, Dc, 0);
        bgemm_kernel<<<gD, 256>>>(h, swk + oDD, nullptr, k, BT, Dc, Dc, 0);
        bgemm_kernel<<<gD, 256>>>(h, swv + oDD, nullptr, v, BT, Dc, Dc, 0);
        // NOTE: rope diagonal is all-ones (theta = x // HD == 0), so K is unchanged.

        attn_kernel<<<dim3(Tc, Bc * Hc), 256>>>(q, k, v, o);

        bgemm_kernel<<<gD, 256>>>(o, swo + oDD,
                                  attn_b + (size_t)l * Dc, x, BT, Dc, Dc, 1);

        rmsnorm_kernel<<<BT, 256>>>(x, n2_w + (size_t)l * Dc, h);

        bgemm_kernel<<<gF, 256>>>(h, sf1 + (size_t)l * Dc * FFc,
                                  f1_b + (size_t)l * FFc, a, BT, FFc, Dc, 0);
        bgemm_kernel<<<gF, 256>>>(a, sfs + (size_t)l * FFc * FFc,
                                  fs_b + (size_t)l * FFc, g, BT, FFc, FFc, 0);
        silu_mul_kernel<<<(BT * FFc) / 256, 256>>>(a, g, BT * FFc);
        bgemm_kernel<<<gD, 256>>>(a, sf2 + (size_t)l * FFc * Dc,
                                  f2_b + (size_t)l * Dc, x, BT, Dc, FFc, 1);
    }

    layernorm_kernel<<<BT, 256>>>(x, ln_w, ln_b, h);
    bgemm_kernel<<<gV, 256>>>(h, sout, out_b, (float*)d_out, BT, Vc, Dc, 0);
}

// round 14
// speedup vs baseline: 4.0289x; 1.6628x over previous
#include <cuda_runtime.h>
#include <cuda_bf16.h>
#include <math.h>
#include <stdint.h>

// Problem constants
#define Bc   2
#define Tc   1024
#define Dc   1024
#define Hc   16
#define HDc  64
#define FFc  4096
#define Lc   2
#define Vc   32000
#define BT   (Bc*Tc)
#define QKVN 3072

#define EPS_RMS 1.1920929e-07f
#define EPS_LN  1e-5f

// ------------------------- device scratch (static, no allocs) -------------
__device__ float    g_x  [BT*Dc];
__device__ float    g_qkv[BT*QKVN];
__device__ float    g_a  [BT*FFc];
__device__ float    g_g  [BT*FFc];
// split-plane activations: [2][rows][K/2] packed bf16 k-pairs
__device__ uint32_t g_hsp[2*BT*(Dc/2)];
__device__ uint32_t g_osp[2*BT*(Dc/2)];
__device__ uint32_t g_asp[2*BT*(FFc/2)];
__device__ uint32_t g_msp[2*BT*(FFc/2)];
// split weights: [L][2][N][K/2]
__device__ uint32_t g_swqkv[(size_t)Lc*2*QKVN*(Dc/2)];
__device__ uint32_t g_swo  [(size_t)Lc*2*Dc*(Dc/2)];
__device__ uint32_t g_sf1  [(size_t)Lc*2*FFc*(Dc/2)];
__device__ uint32_t g_sfs  [(size_t)Lc*2*FFc*(FFc/2)];
__device__ uint32_t g_sf2  [(size_t)Lc*2*Dc*(FFc/2)];
__device__ uint32_t g_sout [(size_t)2*Vc*(Dc/2)];

// ------------------------- helpers ---------------------------------------
__device__ __forceinline__ float warpMax(float v) {
    #pragma unroll
    for (int o = 16; o; o >>= 1) v = fmaxf(v, __shfl_xor_sync(0xffffffffu, v, o));
    return v;
}
__device__ __forceinline__ float warpSum(float v) {
    #pragma unroll
    for (int o = 16; o; o >>= 1) v += __shfl_xor_sync(0xffffffffu, v, o);
    return v;
}
__device__ __forceinline__ void split2(float x0, float x1, uint32_t& hi, uint32_t& lo) {
    __nv_bfloat162 h = __floats2bfloat162_rn(x0, x1);
    float r0 = x0 - __bfloat162float(h.x);
    float r1 = x1 - __bfloat162float(h.y);
    __nv_bfloat162 l = __floats2bfloat162_rn(r0, r1);
    hi = *(uint32_t*)&h;
    lo = *(uint32_t*)&l;
}
__device__ __forceinline__ void mma_bf16(float* c, const uint32_t* a, const uint32_t* b) {
    asm volatile(
        "mma.sync.aligned.m16n8k16.row.col.f32.bf16.bf16.f32 "
        "{%0,%1,%2,%3}, {%4,%5,%6,%7}, {%8,%9}, {%0,%1,%2,%3};"
        : "+f"(c[0]), "+f"(c[1]), "+f"(c[2]), "+f"(c[3])
        : "r"(a[0]), "r"(a[1]), "r"(a[2]), "r"(a[3]),
          "r"(b[0]), "r"(b[1]));
}
__device__ __forceinline__ void ldsm_x4(uint32_t* r, uint32_t addr) {
    asm volatile("ldmatrix.sync.aligned.m8n8.x4.shared.b16 {%0,%1,%2,%3}, [%4];"
        : "=r"(r[0]), "=r"(r[1]), "=r"(r[2]), "=r"(r[3]) : "r"(addr));
}
__device__ __forceinline__ uint32_t smem_u32(const void* p) {
    uint32_t a;
    asm("{ .reg .u64 t; cvta.to.shared.u64 t, %1; cvt.u32.u64 %0, t; }"
        : "=r"(a) : "l"(p));
    return a;
}
__device__ __forceinline__ void cpa16(uint32_t dst, const void* src) {
    asm volatile("cp.async.cg.shared.global [%0], [%1], 16;"
        :: "r"(dst), "l"(src) : "memory");
}

// ------------------------- weight transpose+split -------------------------
// W [K][N] fp32 (layer z) -> S [2][N][K/2] packed bf16-pair planes
__global__ void wsplit_t(const float* __restrict__ W, uint32_t* __restrict__ S,
                         int K, int N, size_t lsw, size_t lss) {
    const float* Wl = W + (size_t)blockIdx.z * lsw;
    uint32_t*    Sl = S + (size_t)blockIdx.z * lss;
    int k0 = blockIdx.y * 64, n0 = blockIdx.x * 32;
    __shared__ float ts[64][33];
    int tid = threadIdx.x;
    #pragma unroll
    for (int i = 0; i < 8; i++) {
        int e = tid + i * 256;
        ts[e >> 5][e & 31] = Wl[(size_t)(k0 + (e >> 5)) * N + n0 + (e & 31)];
    }
    __syncthreads();
    size_t pl = (size_t)N * (K >> 1);
    #pragma unroll
    for (int i = 0; i < 4; i++) {
        int e = tid + i * 256;
        int nn = e >> 5, kp = e & 31;
        uint32_t hi, lo;
        split2(ts[2 * kp][nn], ts[2 * kp + 1][nn], hi, lo);
        size_t o = (size_t)(n0 + nn) * (K >> 1) + (k0 >> 1) + kp;
        Sl[o] = hi; Sl[pl + o] = lo;
    }
}

// qkv weights: [L][H][D][HD] -> merged [L][2][3072][512]; sec 0=q,1=k,2=v
__global__ void wsplit_qkv(const float* __restrict__ W, uint32_t* __restrict__ S, int sec) {
    int l = blockIdx.z >> 4, h = blockIdx.z & 15;
    const float* Wl = W + ((size_t)(l * Hc + h)) * Dc * HDc;
    uint32_t*    Sl = S + (size_t)l * 2 * QKVN * (Dc / 2);
    int k0 = blockIdx.y * 64, n0 = blockIdx.x * 32;
    __shared__ float ts[64][33];
    int tid = threadIdx.x;
    #pragma unroll
    for (int i = 0; i < 8; i++) {
        int e = tid + i * 256;
        ts[e >> 5][e & 31] = Wl[(size_t)(k0 + (e >> 5)) * HDc + n0 + (e & 31)];
    }
    __syncthreads();
    size_t pl = (size_t)QKVN * (Dc / 2);
    #pragma unroll
    for (int i = 0; i < 4; i++) {
        int e = tid + i * 256;
        int nn = e >> 5, kp = e & 31;
        uint32_t hi, lo;
        split2(ts[2 * kp][nn], ts[2 * kp + 1][nn], hi, lo);
        int nrow = sec * 1024 + h * HDc + n0 + nn;
        size_t o = (size_t)nrow * (Dc / 2) + (k0 >> 1) + kp;
        Sl[o] = hi; Sl[pl + o] = lo;
    }
}

// ------------------------- embedding gather -------------------------------
__global__ void embed_kernel(const int* __restrict__ idx, const float* __restrict__ emb) {
    int i = blockIdx.x * blockDim.x + threadIdx.x;
    if (i >= BT * Dc) return;
    int row = i >> 10;
    int d   = i & 1023;
    g_x[i] = emb[(size_t)idx[row] * Dc + d];
}

// ------------------------- RMSNorm -> split planes ------------------------
__global__ void rmsnorm_sp(const float* __restrict__ x, const float* __restrict__ w,
                           uint32_t* __restrict__ sp) {
    int row = blockIdx.x, tid = threadIdx.x;
    const float4* xr = (const float4*)(x + (size_t)row * Dc);
    float4 v = xr[tid];
    float ss = v.x*v.x + v.y*v.y + v.z*v.z + v.w*v.w;
    __shared__ float sred[8];
    ss = warpSum(ss);
    if ((tid & 31) == 0) sred[tid >> 5] = ss;
    __syncthreads();
    if (tid == 0) {
        float t = 0.f;
        #pragma unroll
        for (int i = 0; i < 8; i++) t += sred[i];
        sred[0] = rsqrtf(t * (1.0f / Dc) + EPS_RMS);
    }
    __syncthreads();
    float r = sred[0];
    float4 ww = ((const float4*)w)[tid];
    float y0 = v.x*r*ww.x, y1 = v.y*r*ww.y, y2 = v.z*r*ww.z, y3 = v.w*r*ww.w;
    size_t o = (size_t)row * (Dc/2) + tid * 2;
    size_t pl = (size_t)BT * (Dc/2);
    uint32_t hi, lo;
    split2(y0, y1, hi, lo); sp[o]   = hi; sp[pl+o]   = lo;
    split2(y2, y3, hi, lo); sp[o+1] = hi; sp[pl+o+1] = lo;
}

// ------------------------- LayerNorm -> split planes ----------------------
__global__ void layernorm_sp(const float* __restrict__ x, const float* __restrict__ w,
                             const float* __restrict__ b, uint32_t* __restrict__ sp) {
    int row = blockIdx.x, tid = threadIdx.x;
    const float4* xr = (const float4*)(x + (size_t)row * Dc);
    float4 v = xr[tid];
    __shared__ float sred[8];
    __shared__ float sbc[2];
    float s = v.x + v.y + v.z + v.w;
    s = warpSum(s);
    if ((tid & 31) == 0) sred[tid >> 5] = s;
    __syncthreads();
    if (tid == 0) {
        float t = 0.f;
        #pragma unroll
        for (int i = 0; i < 8; i++) t += sred[i];
        sbc[0] = t * (1.0f / Dc);
    }
    __syncthreads();
    float mu = sbc[0];
    float d0 = v.x-mu, d1 = v.y-mu, d2 = v.z-mu, d3 = v.w-mu;
    float sq = d0*d0 + d1*d1 + d2*d2 + d3*d3;
    sq = warpSum(sq);
    if ((tid & 31) == 0) sred[tid >> 5] = sq;
    __syncthreads();
    if (tid == 0) {
        float t = 0.f;
        #pragma unroll
        for (int i = 0; i < 8; i++) t += sred[i];
        sbc[1] = rsqrtf(t * (1.0f / Dc) + EPS_LN);
    }
    __syncthreads();
    float r = sbc[1];
    float4 ww = ((const float4*)w)[tid];
    float4 bb = ((const float4*)b)[tid];
    float y0 = d0*r*ww.x + bb.x, y1 = d1*r*ww.y + bb.y;
    float y2 = d2*r*ww.z + bb.z, y3 = d3*r*ww.w + bb.w;
    size_t o = (size_t)row * (Dc/2) + tid * 2;
    size_t pl = (size_t)BT * (Dc/2);
    uint32_t hi, lo;
    split2(y0, y1, hi, lo); sp[o]   = hi; sp[pl+o]   = lo;
    split2(y2, y3, hi, lo); sp[o+1] = hi; sp[pl+o+1] = lo;
}

// ------------------------- SiLU(a)*g -> split planes ----------------------
__global__ void silu_sp(const float* __restrict__ a, const float* __restrict__ g,
                        uint32_t* __restrict__ sp, int n4) {
    int i = blockIdx.x * blockDim.x + threadIdx.x;
    if (i >= n4) return;
    float4 av = ((const float4*)a)[i];
    float4 gv = ((const float4*)g)[i];
    float m0 = (av.x / (1.0f + expf(-av.x))) * gv.x;
    float m1 = (av.y / (1.0f + expf(-av.y))) * gv.y;
    float m2 = (av.z / (1.0f + expf(-av.z))) * gv.z;
    float m3 = (av.w / (1.0f + expf(-av.w))) * gv.w;
    size_t o = (size_t)i * 2;
    size_t pl = (size_t)BT * (FFc/2);
    uint32_t hi, lo;
    split2(m0, m1, hi, lo); sp[o]   = hi; sp[pl+o]   = lo;
    split2(m2, m3, hi, lo); sp[o+1] = hi; sp[pl+o+1] = lo;
}

// ------------------------- tiled flash attention --------------------------
// grid (T/8, B*H), 256 thr; warp w handles q row t0+w.
// qkv: [B*T][3072] fp32 (q|k|v). Writes o as split planes [2][BT][Dc/2].
__global__ void __launch_bounds__(256) attn_kernel(const float* __restrict__ qkv,
                                                   uint32_t* __restrict__ osp) {
    __shared__ float Ks[64][68];
    __shared__ float Vs[64][68];
    __shared__ float qs[8][68];
    int tid = threadIdx.x, wid = tid >> 5, lane = tid & 31;
    int bh = blockIdx.y, b = bh >> 4, h = bh & 15;
    int t0 = blockIdx.x << 3;
    int t = t0 + wid;
    const float* base = qkv + (size_t)b * Tc * QKVN;

    if (tid < 128) {
        int r = tid >> 4, c4 = tid & 15;
        const float4* src = (const float4*)(base + (size_t)(t0 + r) * QKVN + h * HDc);
        *(float4*)&qs[r][c4 * 4] = src[c4];
    }

    float m = -INFINITY, l = 0.f, o0 = 0.f, o1 = 0.f;
    int nCh = ((t0 + 7) >> 6) + 1;

    for (int ch = 0; ch < nCh; ch++) {
        int sb = ch << 6;
        __syncthreads();
        #pragma unroll
        for (int i = 0; i < 4; i++) {
            int e = tid + i * 256;            // 0..1023
            int r = e >> 4, c4 = e & 15;
            const float* rowp = base + (size_t)(sb + r) * QKVN + h * HDc;
            *(float4*)&Ks[r][c4 * 4] = ((const float4*)(rowp + Dc))[c4];
            *(float4*)&Vs[r][c4 * 4] = ((const float4*)(rowp + 2 * Dc))[c4];
        }
        __syncthreads();

        float sc0 = 0.f, sc1 = 0.f;
        const float4* q4  = (const float4*)qs[wid];
        const float4* k40 = (const float4*)Ks[lane];
        const float4* k41 = (const float4*)Ks[lane + 32];
        #pragma unroll
        for (int d = 0; d < 16; d++) {
            float4 qv = q4[d], ka = k40[d], kb = k41[d];
            sc0 += qv.x*ka.x + qv.y*ka.y + qv.z*ka.z + qv.w*ka.w;
            sc1 += qv.x*kb.x + qv.y*kb.y + qv.z*kb.z + qv.w*kb.w;
        }
        sc0 = (sb + lane      <= t) ? sc0 * 0.125f : -INFINITY;
        sc1 = (sb + 32 + lane <= t) ? sc1 * 0.125f : -INFINITY;

        float mch  = warpMax(fmaxf(sc0, sc1));
        float mnew = fmaxf(m, mch);
        float alpha = __expf(m - mnew);
        float p0 = __expf(sc0 - mnew);
        float p1 = __expf(sc1 - mnew);
        l = l * alpha + warpSum(p0 + p1);
        o0 *= alpha; o1 *= alpha;
        m = mnew;
        #pragma unroll
        for (int s = 0; s < 32; s++) {
            float p = __shfl_sync(0xffffffffu, p0, s);
            float2 vv = *(const float2*)&Vs[s][lane * 2];
            o0 += p * vv.x; o1 += p * vv.y;
        }
        #pragma unroll
        for (int s = 0; s < 32; s++) {
            float p = __shfl_sync(0xffffffffu, p1, s);
            float2 vv = *(const float2*)&Vs[s + 32][lane * 2];
            o0 += p * vv.x; o1 += p * vv.y;
        }
    }

    float inv = 1.0f / l;
    uint32_t hi, lo;
    split2(o0 * inv, o1 * inv, hi, lo);
    size_t orow = (size_t)(b * Tc + t) * (Dc/2) + h * 32 + lane;
    osp[orow] = hi;
    osp[(size_t)BT * (Dc/2) + orow] = lo;
}

// ------------------------- bf16x3 mma.sync GEMM ---------------------------
// C = A @ B: Asp [2][M][K/2], Bsp [2][N][K/2]. 128x128 tile, BK=32,
// 3-stage cp.async pipeline, ldmatrix fragments, 8 warps (4m x 2n).
#define F_F32 1
#define F_RES 2
#define F_SPL 4
#define OP_AH 0
#define OP_AL 8192
#define OP_BH 16384
#define OP_BL 24576
#define STGB  32768
#define GEMM_SMEM (3*STGB)

__device__ __forceinline__ uint32_t swz_addr(int row, int c) {
    return (uint32_t)(row * 64 + ((c * 16) ^ (((row >> 1) & 3) << 4)));
}

__global__ void __launch_bounds__(256, 2) tc_gemm(
    const uint32_t* __restrict__ Asp, const uint32_t* __restrict__ Bsp,
    const float* __restrict__ bias, float* __restrict__ Cf,
    uint32_t* __restrict__ Csp,
    int M, int N, int K, int flags)
{
    extern __shared__ char smem[];
    uint32_t smem0 = smem_u32(smem);
    int tid = threadIdx.x, wid = tid >> 5, lane = tid & 31;
    int m0 = blockIdx.y << 7, n0 = blockIdx.x << 7;
    int Kh = K >> 1;
    size_t planeA = (size_t)M * Kh, planeB = (size_t)N * Kh;
    const uint32_t* Ag = Asp + (size_t)m0 * Kh;
    const uint32_t* Bg = Bsp + (size_t)n0 * Kh;
    int nCh = K >> 5;

    int r0 = tid >> 2, c0 = tid & 3;
    int r1 = r0 + 64;

    auto load_st = [&](int ch, int st) {
        uint32_t sb = smem0 + st * STGB;
        int kofs = ch * 16 + c0 * 4;
        const uint32_t* a0 = Ag + (size_t)r0 * Kh + kofs;
        const uint32_t* a1 = Ag + (size_t)r1 * Kh + kofs;
        const uint32_t* b0 = Bg + (size_t)r0 * Kh + kofs;
        const uint32_t* b1 = Bg + (size_t)r1 * Kh + kofs;
        uint32_t s0 = swz_addr(r0, c0), s1 = swz_addr(r1, c0);
        cpa16(sb + OP_AH + s0, a0);
        cpa16(sb + OP_AH + s1, a1);
        cpa16(sb + OP_AL + s0, a0 + planeA);
        cpa16(sb + OP_AL + s1, a1 + planeA);
        cpa16(sb + OP_BH + s0, b0);
        cpa16(sb + OP_BH + s1, b1);
        cpa16(sb + OP_BL + s0, b0 + planeB);
        cpa16(sb + OP_BL + s1, b1 + planeB);
        asm volatile("cp.async.commit_group;" ::: "memory");
    };

    float acc[2][8][4];
    #pragma unroll
    for (int i = 0; i < 2; i++)
        #pragma unroll
        for (int j = 0; j < 8; j++)
            #pragma unroll
            for (int r = 0; r < 4; r++) acc[i][j][r] = 0.f;

    int wm = (wid & 3) << 5, wn = (wid >> 2) << 6;
    int lrow = lane & 15, lhalf = lane >> 4;

    load_st(0, 0);
    load_st(1, 1);

    for (int ch = 0; ch < nCh; ch++) {
        if (ch + 2 < nCh) {
            asm volatile("cp.async.wait_group 1;" ::: "memory");
        } else {
            asm volatile("cp.async.wait_group 0;" ::: "memory");
        }
        __syncthreads();
        uint32_t sb = smem0 + (ch % 3) * STGB;
        #pragma unroll
        for (int ks = 0; ks < 2; ks++) {
            int c = ks * 2 + lhalf;
            uint32_t ah[2][4], al[2][4], bq[4][4];
            #pragma unroll
            for (int i = 0; i < 2; i++) {
                int row = wm + i * 16 + lrow;
                uint32_t sa = swz_addr(row, c);
                ldsm_x4(ah[i], sb + OP_AH + sa);
                ldsm_x4(al[i], sb + OP_AL + sa);
            }
            #pragma unroll
            for (int jj = 0; jj < 4; jj++)
                ldsm_x4(bq[jj], sb + OP_BH + swz_addr(wn + jj * 16 + lrow, c));
            #pragma unroll
            for (int jj = 0; jj < 4; jj++) {
                uint32_t bf0[2] = {bq[jj][0], bq[jj][2]};
                uint32_t bf1[2] = {bq[jj][1], bq[jj][3]};
                #pragma unroll
                for (int i = 0; i < 2; i++) {
                    mma_bf16(acc[i][2*jj],   ah[i], bf0);
                    mma_bf16(acc[i][2*jj+1], ah[i], bf1);
                    mma_bf16(acc[i][2*jj],   al[i], bf0);
                    mma_bf16(acc[i][2*jj+1], al[i], bf1);
                }
            }
            #pragma unroll
            for (int jj = 0; jj < 4; jj++)
                ldsm_x4(bq[jj], sb + OP_BL + swz_addr(wn + jj * 16 + lrow, c));
            #pragma unroll
            for (int jj = 0; jj < 4; jj++) {
                uint32_t bf0[2] = {bq[jj][0], bq[jj][2]};
                uint32_t bf1[2] = {bq[jj][1], bq[jj][3]};
                #pragma unroll
                for (int i = 0; i < 2; i++) {
                    mma_bf16(acc[i][2*jj],   ah[i], bf0);
                    mma_bf16(acc[i][2*jj+1], ah[i], bf1);
                }
            }
        }
        if (ch + 2 < nCh) load_st(ch + 2, (ch + 2) % 3);
    }

    // epilogue
    int erow = lane >> 2;
    int ecol = (lane & 3) * 2;
    size_t splPl = (size_t)M * (N >> 1);
    #pragma unroll
    for (int i = 0; i < 2; i++) {
        int row = m0 + wm + i * 16 + erow;
        #pragma unroll
        for (int j = 0; j < 8; j++) {
            int col = n0 + wn + j * 8 + ecol;
            float b0 = 0.f, b1 = 0.f;
            if (bias) { b0 = bias[col]; b1 = bias[col + 1]; }
            float v00 = acc[i][j][0] + b0, v01 = acc[i][j][1] + b1;
            float v10 = acc[i][j][2] + b0, v11 = acc[i][j][3] + b1;
            size_t o0 = (size_t)row * N + col;
            size_t o1 = (size_t)(row + 8) * N + col;
            if (flags & F_RES) {
                v00 += Cf[o0]; v01 += Cf[o0 + 1];
                v10 += Cf[o1]; v11 += Cf[o1 + 1];
            }
            if (flags & F_F32) {
                Cf[o0] = v00; Cf[o0 + 1] = v01;
                Cf[o1] = v10; Cf[o1 + 1] = v11;
            }
            if (flags & F_SPL) {
                size_t p0 = (size_t)row * (N >> 1) + (col >> 1);
                size_t p1 = (size_t)(row + 8) * (N >> 1) + (col >> 1);
                uint32_t hi, lo;
                split2(v00, v01, hi, lo); Csp[p0] = hi; Csp[splPl + p0] = lo;
                split2(v10, v11, hi, lo); Csp[p1] = hi; Csp[splPl + p1] = lo;
            }
        }
    }
}

// ------------------------- host orchestration -----------------------------
extern "C" void kernel_launch(void* const* d_in, const int* in_sizes, int n_in,
                              void* d_out, int out_size) {
    const int*   idx    = (const int*)  d_in[0];
    const float* emb    = (const float*)d_in[1];
    const float* wq     = (const float*)d_in[2];
    const float* wk     = (const float*)d_in[3];
    const float* wv     = (const float*)d_in[4];
    const float* attn_w = (const float*)d_in[5];
    const float* attn_b = (const float*)d_in[6];
    const float* n1_w   = (const float*)d_in[7];
    const float* n2_w   = (const float*)d_in[8];
    const float* f1_w   = (const float*)d_in[9];
    const float* f1_b   = (const float*)d_in[10];
    const float* fs_w   = (const float*)d_in[11];
    const float* fs_b   = (const float*)d_in[12];
    const float* f2_w   = (const float*)d_in[13];
    const float* f2_b   = (const float*)d_in[14];
    const float* ln_w   = (const float*)d_in[15];
    const float* ln_b   = (const float*)d_in[16];
    const float* out_w  = (const float*)d_in[17];
    const float* out_b  = (const float*)d_in[18];

    float *x, *qkv, *a, *g;
    uint32_t *hsp, *osp, *asp, *msp;
    uint32_t *swqkv, *swo, *sf1, *sfs, *sf2, *sout;
    cudaGetSymbolAddress((void**)&x,    g_x);
    cudaGetSymbolAddress((void**)&qkv,  g_qkv);
    cudaGetSymbolAddress((void**)&a,    g_a);
    cudaGetSymbolAddress((void**)&g,    g_g);
    cudaGetSymbolAddress((void**)&hsp,  g_hsp);
    cudaGetSymbolAddress((void**)&osp,  g_osp);
    cudaGetSymbolAddress((void**)&asp,  g_asp);
    cudaGetSymbolAddress((void**)&msp,  g_msp);
    cudaGetSymbolAddress((void**)&swqkv,g_swqkv);
    cudaGetSymbolAddress((void**)&swo,  g_swo);
    cudaGetSymbolAddress((void**)&sf1,  g_sf1);
    cudaGetSymbolAddress((void**)&sfs,  g_sfs);
    cudaGetSymbolAddress((void**)&sf2,  g_sf2);
    cudaGetSymbolAddress((void**)&sout, g_sout);

    cudaFuncSetAttribute(tc_gemm,
                         cudaFuncAttributeMaxDynamicSharedMemorySize, GEMM_SMEM);

    // weight splits (transposed [N][K/2] planes)
    wsplit_qkv<<<dim3(2, 16, Lc * Hc), 256>>>(wq, swqkv, 0);
    wsplit_qkv<<<dim3(2, 16, Lc * Hc), 256>>>(wk, swqkv, 1);
    wsplit_qkv<<<dim3(2, 16, Lc * Hc), 256>>>(wv, swqkv, 2);
    wsplit_t<<<dim3(Dc/32,  Dc/64,  Lc), 256>>>(attn_w, swo, Dc,  Dc,
        (size_t)Dc*Dc,   (size_t)2*Dc*(Dc/2));
    wsplit_t<<<dim3(FFc/32, Dc/64,  Lc), 256>>>(f1_w,   sf1, Dc,  FFc,
        (size_t)Dc*FFc,  (size_t)2*FFc*(Dc/2));
    wsplit_t<<<dim3(FFc/32, FFc/64, Lc), 256>>>(fs_w,   sfs, FFc, FFc,
        (size_t)FFc*FFc, (size_t)2*FFc*(FFc/2));
    wsplit_t<<<dim3(Dc/32,  FFc/64, Lc), 256>>>(f2_w,   sf2, FFc, Dc,
        (size_t)FFc*Dc,  (size_t)2*Dc*(FFc/2));
    wsplit_t<<<dim3(Vc/32,  Dc/64,  1),  256>>>(out_w,  sout, Dc, Vc, 0, 0);

    embed_kernel<<<(BT * Dc) / 256, 256>>>(idx, emb);

    dim3 gQKV(QKVN/128, BT/128);
    dim3 gD(Dc/128, BT/128);
    dim3 gF(FFc/128, BT/128);
    dim3 gV(Vc/128, BT/128);

    for (int l = 0; l < Lc; l++) {
        uint32_t* wqkv_l = swqkv + (size_t)l * 2 * QKVN * (Dc/2);
        uint32_t* swo_l  = swo   + (size_t)l * 2 * Dc   * (Dc/2);
        uint32_t* sf1_l  = sf1   + (size_t)l * 2 * FFc  * (Dc/2);
        uint32_t* sfs_l  = sfs   + (size_t)l * 2 * FFc  * (FFc/2);
        uint32_t* sf2_l  = sf2   + (size_t)l * 2 * Dc   * (FFc/2);

        rmsnorm_sp<<<BT, 256>>>(x, n1_w + (size_t)l * Dc, hsp);
        tc_gemm<<<gQKV, 256, GEMM_SMEM>>>(hsp, wqkv_l, nullptr, qkv, nullptr,
                                          BT, QKVN, Dc, F_F32);
        // rope diagonal is all-ones (theta = x // HD == 0): K unchanged.
        attn_kernel<<<dim3(Tc/8, Bc*Hc), 256>>>(qkv, osp);
        tc_gemm<<<gD, 256, GEMM_SMEM>>>(osp, swo_l, attn_b + (size_t)l * Dc,
                                        x, nullptr, BT, Dc, Dc, F_F32 | F_RES);

        rmsnorm_sp<<<BT, 256>>>(x, n2_w + (size_t)l * Dc, hsp);
        tc_gemm<<<gF, 256, GEMM_SMEM>>>(hsp, sf1_l, f1_b + (size_t)l * FFc,
                                        a, asp, BT, FFc, Dc, F_F32 | F_SPL);
        tc_gemm<<<gF, 256, GEMM_SMEM>>>(asp, sfs_l, fs_b + (size_t)l * FFc,
                                        g, nullptr, BT, FFc, FFc, F_F32);
        silu_sp<<<(BT * FFc / 4 + 255) / 256, 256>>>(a, g, msp, BT * FFc / 4);
        tc_gemm<<<gD, 256, GEMM_SMEM>>>(msp, sf2_l, f2_b + (size_t)l * Dc,
                                        x, nullptr, BT, Dc, FFc, F_F32 | F_RES);
    }

    layernorm_sp<<<BT, 256>>>(x, ln_w, ln_b, hsp);
    tc_gemm<<<gV, 256, GEMM_SMEM>>>(hsp, sout, out_b, (float*)d_out, nullptr,
                                    BT, Vc, Dc, F_F32);
}